// round 1
// baseline (speedup 1.0000x reference)
#include <cuda_runtime.h>
#include <math.h>

#define B_    16
#define C_    256
#define H_    64
#define W_    64
#define K_    7
#define HW_   (H_*W_)      // 4096
#define KK_   (K_*K_)      // 49
#define CKK_  (C_*KK_)     // 12544
#define CMID_ 64

// ---- scratch (static device globals; no allocation) ----
__device__ float g_pooled[B_*C_];          // [B,C]
__device__ float g_h[B_*CMID_];            // [B,64]
__device__ float g_fused[B_*CKK_];         // [B,C,49]
__device__ float g_dw[(size_t)B_*C_*HW_];  // [B,C,H,W]  (67 MB)

// ============================================================
// 1) global average pool: one block per (b,c), reduce 4096 floats
// ============================================================
__global__ void pool_kernel(const float* __restrict__ x) {
    int bc = blockIdx.x;
    const float4* xp = (const float4*)(x + (size_t)bc * HW_);
    int t = threadIdx.x;
    float s = 0.f;
#pragma unroll
    for (int it = 0; it < 4; it++) {
        float4 v = xp[t + it * 256];
        s += v.x + v.y + v.z + v.w;
    }
#pragma unroll
    for (int o = 16; o > 0; o >>= 1) s += __shfl_down_sync(0xffffffffu, s, o);
    __shared__ float ws[8];
    if ((t & 31) == 0) ws[t >> 5] = s;
    __syncthreads();
    if (t < 8) {
        float v = ws[t];
#pragma unroll
        for (int o = 4; o > 0; o >>= 1) v += __shfl_down_sync(0xffu, v, o);
        if (t == 0) g_pooled[bc] = v * (1.f / (float)HW_);
    }
}

// ============================================================
// 2) h = gelu(pooled @ w1.T + b1), exact GELU. one block per b, 64 threads
// ============================================================
__global__ void mlp_kernel(const float* __restrict__ w1, const float* __restrict__ b1) {
    int b = blockIdx.x;
    __shared__ float ps[C_];
    int t = threadIdx.x;
    for (int i = t; i < C_; i += 64) ps[i] = g_pooled[b * C_ + i];
    __syncthreads();
    float acc = b1[t];
    const float* wr = w1 + t * C_;
#pragma unroll 8
    for (int kk = 0; kk < C_; kk++) acc += ps[kk] * wr[kk];
    float g = 0.5f * acc * (1.f + erff(acc * 0.70710678118654752f));
    g_h[b * CMID_ + t] = g;
}

// ============================================================
// 3) fused[b, c*49+i] = dw[c*49+i] + b2[r] + h[b,:]·w2[r,:]
// ============================================================
__global__ void genw_kernel(const float* __restrict__ dw,
                            const float* __restrict__ w2,
                            const float* __restrict__ b2) {
    int b = blockIdx.y;
    int r = blockIdx.x * 128 + threadIdx.x;   // 98*128 = 12544
    __shared__ float hs[CMID_];
    if (threadIdx.x < CMID_) hs[threadIdx.x] = g_h[b * CMID_ + threadIdx.x];
    __syncthreads();
    float acc = b2[r] + dw[r];
    const float* wr = w2 + (size_t)r * CMID_;
#pragma unroll
    for (int kk = 0; kk < CMID_; kk++) acc += hs[kk] * wr[kk];
    g_fused[b * CKK_ + r] = acc;
}

// ============================================================
// 4) per-instance depthwise 7x7, zero pad 3. one block per (b,c).
//    70x70 haloed plane in smem; each thread computes a 1x16 strip.
// ============================================================
__global__ void dwconv_kernel(const float* __restrict__ x) {
    __shared__ float sp[70 * 70];
    __shared__ float ws[KK_];
    int bc = blockIdx.x;
    int b = bc >> 8, c = bc & 255;
    const float* xp = x + (size_t)bc * HW_;
    int t = threadIdx.x;
    if (t < KK_) ws[t] = g_fused[b * CKK_ + c * KK_ + t];
    for (int s = t; s < 70 * 70; s += 256) {
        int r = s / 70, cc = s - r * 70;
        int gy = r - 3, gx = cc - 3;
        float v = 0.f;
        if (gy >= 0 && gy < H_ && gx >= 0 && gx < W_) v = xp[gy * W_ + gx];
        sp[s] = v;
    }
    __syncthreads();

    int row = t >> 2, col0 = (t & 3) * 16;
    float acc[16];
#pragma unroll
    for (int o = 0; o < 16; o++) acc[o] = 0.f;
#pragma unroll
    for (int i = 0; i < K_; i++) {
        float wr[K_];
#pragma unroll
        for (int j = 0; j < K_; j++) wr[j] = ws[i * K_ + j];
        float xv[22];
        const float* rp = &sp[(row + i) * 70 + col0];
#pragma unroll
        for (int q = 0; q < 22; q++) xv[q] = rp[q];
#pragma unroll
        for (int j = 0; j < K_; j++)
#pragma unroll
            for (int o = 0; o < 16; o++)
                acc[o] += xv[o + j] * wr[j];
    }
    float* op = g_dw + (size_t)bc * HW_ + row * W_ + col0;
#pragma unroll
    for (int o = 0; o < 16; o += 4)
        *(float4*)(op + o) = make_float4(acc[o], acc[o + 1], acc[o + 2], acc[o + 3]);
}

// ============================================================
// 5) pointwise: Y[b,o,hw] = sum_c PW[o,c] * S[b,c,hw]
//    batched SGEMM: M=256(o), N=4096(hw), K=256(c)
//    128x128 block tile, TK=8, 8x8 per thread, double-buffered smem.
// ============================================================
__global__ void __launch_bounds__(256)
pw_gemm_kernel(const float* __restrict__ A, float* __restrict__ out) {
    __shared__ float As[2][8 * 132];   // [k][m], padded pitch 132
    __shared__ float Bs[2][8 * 128];   // [k][n]

    int tid = threadIdx.x;
    int m0 = blockIdx.y * 128;
    int n0 = blockIdx.x * 128;
    int b  = blockIdx.z;
    const float* Bm = g_dw + (size_t)b * C_ * HW_;

    int aRow = tid >> 1;           // 0..127 (m)
    int aCol = (tid & 1) * 4;      // k offset 0/4
    int bRow = tid >> 5;           // 0..7  (k)
    int bCol = (tid & 31) * 4;     // 0..124 (n)

    { // prologue: tile 0
        float4 av = *(const float4*)(A + (size_t)(m0 + aRow) * C_ + aCol);
        As[0][(aCol + 0) * 132 + aRow] = av.x;
        As[0][(aCol + 1) * 132 + aRow] = av.y;
        As[0][(aCol + 2) * 132 + aRow] = av.z;
        As[0][(aCol + 3) * 132 + aRow] = av.w;
        float4 bv = *(const float4*)(Bm + (size_t)bRow * HW_ + n0 + bCol);
        *(float4*)&Bs[0][bRow * 128 + bCol] = bv;
    }
    __syncthreads();

    float acc[8][8];
#pragma unroll
    for (int i = 0; i < 8; i++)
#pragma unroll
        for (int j = 0; j < 8; j++) acc[i][j] = 0.f;

    int ty = tid >> 4, tx = tid & 15;
    int buf = 0;
    const int NT = C_ / 8;  // 32
    for (int t = 0; t < NT; t++) {
        float4 av, bv;
        if (t < NT - 1) {
            int k0 = (t + 1) * 8;
            av = *(const float4*)(A + (size_t)(m0 + aRow) * C_ + k0 + aCol);
            bv = *(const float4*)(Bm + (size_t)(k0 + bRow) * HW_ + n0 + bCol);
        }
#pragma unroll
        for (int k = 0; k < 8; k++) {
            float a[8], bb[8];
            *(float4*)&a[0]  = *(float4*)&As[buf][k * 132 + ty * 8];
            *(float4*)&a[4]  = *(float4*)&As[buf][k * 132 + ty * 8 + 4];
            *(float4*)&bb[0] = *(float4*)&Bs[buf][k * 128 + tx * 8];
            *(float4*)&bb[4] = *(float4*)&Bs[buf][k * 128 + tx * 8 + 4];
#pragma unroll
            for (int i = 0; i < 8; i++)
#pragma unroll
                for (int j = 0; j < 8; j++)
                    acc[i][j] += a[i] * bb[j];
        }
        if (t < NT - 1) {
            buf ^= 1;
            As[buf][(aCol + 0) * 132 + aRow] = av.x;
            As[buf][(aCol + 1) * 132 + aRow] = av.y;
            As[buf][(aCol + 2) * 132 + aRow] = av.z;
            As[buf][(aCol + 3) * 132 + aRow] = av.w;
            *(float4*)&Bs[buf][bRow * 128 + bCol] = bv;
            __syncthreads();
        }
    }

    float* Cp = out + (size_t)b * C_ * HW_ + (size_t)(m0 + ty * 8) * HW_ + n0 + tx * 8;
#pragma unroll
    for (int i = 0; i < 8; i++) {
        *(float4*)(Cp + (size_t)i * HW_)     = make_float4(acc[i][0], acc[i][1], acc[i][2], acc[i][3]);
        *(float4*)(Cp + (size_t)i * HW_ + 4) = make_float4(acc[i][4], acc[i][5], acc[i][6], acc[i][7]);
    }
}

// ============================================================
extern "C" void kernel_launch(void* const* d_in, const int* in_sizes, int n_in,
                              void* d_out, int out_size) {
    const float* x  = (const float*)d_in[0];
    const float* dw = (const float*)d_in[1];
    const float* pw = (const float*)d_in[2];
    const float* w1 = (const float*)d_in[3];
    const float* b1 = (const float*)d_in[4];
    const float* w2 = (const float*)d_in[5];
    const float* b2 = (const float*)d_in[6];
    float* out = (float*)d_out;

    pool_kernel <<<B_ * C_, 256>>>(x);
    mlp_kernel  <<<B_, 64>>>(w1, b1);
    genw_kernel <<<dim3(CKK_ / 128, B_), 128>>>(dw, w2, b2);
    dwconv_kernel<<<B_ * C_, 256>>>(x);
    pw_gemm_kernel<<<dim3(HW_ / 128, C_ / 128, B_), 256>>>(pw, out);
}

// round 11
// speedup vs baseline: 1.2543x; 1.2543x over previous
#include <cuda_runtime.h>
#include <cuda_bf16.h>
#include <mma.h>
#include <cstdint>
#include <math.h>

using namespace nvcuda;

#define B_    16
#define C_    256
#define H_    64
#define W_    64
#define K_    7
#define HW_   (H_*W_)      // 4096
#define KK_   (K_*K_)      // 49
#define CKK_  (C_*KK_)     // 12544
#define CMID_ 64

// ---- scratch (static device globals; no allocation) ----
__device__ float g_pooled[B_*C_];
__device__ float g_h[B_*CMID_];
__device__ float g_fused[B_*CKK_];
__device__ __nv_bfloat16 g_s_hi[(size_t)B_*C_*HW_];   // dwconv out, bf16 hi (33.5 MB)
__device__ __nv_bfloat16 g_s_lo[(size_t)B_*C_*HW_];   // dwconv out, bf16 lo (33.5 MB)
__device__ __nv_bfloat16 g_pw_hi[C_*C_];
__device__ __nv_bfloat16 g_pw_lo[C_*C_];

// ============================================================
// 1) global average pool
// ============================================================
__global__ void pool_kernel(const float* __restrict__ x) {
    int bc = blockIdx.x;
    const float4* xp = (const float4*)(x + (size_t)bc * HW_);
    int t = threadIdx.x;
    float s = 0.f;
#pragma unroll
    for (int it = 0; it < 4; it++) {
        float4 v = xp[t + it * 256];
        s += v.x + v.y + v.z + v.w;
    }
#pragma unroll
    for (int o = 16; o > 0; o >>= 1) s += __shfl_down_sync(0xffffffffu, s, o);
    __shared__ float ws[8];
    if ((t & 31) == 0) ws[t >> 5] = s;
    __syncthreads();
    if (t < 8) {
        float v = ws[t];
#pragma unroll
        for (int o = 4; o > 0; o >>= 1) v += __shfl_down_sync(0xffu, v, o);
        if (t == 0) g_pooled[bc] = v * (1.f / (float)HW_);
    }
}

// ============================================================
// 2) h = gelu(pooled @ w1.T + b1), exact GELU
// ============================================================
__global__ void mlp_kernel(const float* __restrict__ w1, const float* __restrict__ b1) {
    int b = blockIdx.x;
    __shared__ float ps[C_];
    int t = threadIdx.x;
    for (int i = t; i < C_; i += 64) ps[i] = g_pooled[b * C_ + i];
    __syncthreads();
    float acc = b1[t];
    const float* wr = w1 + t * C_;
#pragma unroll 8
    for (int kk = 0; kk < C_; kk++) acc += ps[kk] * wr[kk];
    float g = 0.5f * acc * (1.f + erff(acc * 0.70710678118654752f));
    g_h[b * CMID_ + t] = g;
}

// ============================================================
// 3) fused dynamic weights
// ============================================================
__global__ void genw_kernel(const float* __restrict__ dw,
                            const float* __restrict__ w2,
                            const float* __restrict__ b2) {
    int b = blockIdx.y;
    int r = blockIdx.x * 128 + threadIdx.x;
    __shared__ float hs[CMID_];
    if (threadIdx.x < CMID_) hs[threadIdx.x] = g_h[b * CMID_ + threadIdx.x];
    __syncthreads();
    float acc = b2[r] + dw[r];
    const float* wr = w2 + (size_t)r * CMID_;
#pragma unroll
    for (int kk = 0; kk < CMID_; kk++) acc += hs[kk] * wr[kk];
    g_fused[b * CKK_ + r] = acc;
}

// ============================================================
// 3b) split pw weights into bf16 hi/lo
// ============================================================
__global__ void pwsplit_kernel(const float* __restrict__ pw) {
    int i = blockIdx.x * 256 + threadIdx.x;
    float x = pw[i];
    __nv_bfloat16 h = __float2bfloat16(x);
    g_pw_hi[i] = h;
    g_pw_lo[i] = __float2bfloat16(x - __bfloat162float(h));
}

// ============================================================
// 4) per-instance depthwise 7x7 (pitch-72 smem, float4 LDS)
//    Output written directly as bf16 hi/lo pair.
// ============================================================
__global__ void __launch_bounds__(256) dwconv_kernel(const float* __restrict__ x) {
    __shared__ float sp[70 * 72];
    __shared__ float ws[KK_];
    int bc = blockIdx.x;
    int b = bc >> 8, c = bc & 255;
    const float* xp = x + (size_t)bc * HW_;
    int t = threadIdx.x;
    if (t < KK_) ws[t] = g_fused[b * CKK_ + c * KK_ + t];
    for (int s = t; s < 70 * 70; s += 256) {
        int r = s / 70, cc = s - r * 70;
        int gy = r - 3, gx = cc - 3;
        float v = 0.f;
        if (gy >= 0 && gy < H_ && gx >= 0 && gx < W_) v = xp[gy * W_ + gx];
        sp[r * 72 + cc] = v;
    }
    __syncthreads();

    int row = t >> 2, col0 = (t & 3) * 16;
    float acc[16];
#pragma unroll
    for (int o = 0; o < 16; o++) acc[o] = 0.f;
#pragma unroll
    for (int i = 0; i < K_; i++) {
        float wr[K_];
#pragma unroll
        for (int j = 0; j < K_; j++) wr[j] = ws[i * K_ + j];
        float4 xv4[6];
        const float* rp = &sp[(row + i) * 72 + col0];
#pragma unroll
        for (int q = 0; q < 6; q++) xv4[q] = *(const float4*)(rp + q * 4);
        const float* xv = (const float*)xv4;
#pragma unroll
        for (int j = 0; j < K_; j++)
#pragma unroll
            for (int o = 0; o < 16; o++)
                acc[o] += xv[o + j] * wr[j];
    }
    __align__(16) __nv_bfloat16 hi[16], lo[16];
#pragma unroll
    for (int o = 0; o < 16; o++) {
        __nv_bfloat16 h = __float2bfloat16(acc[o]);
        hi[o] = h;
        lo[o] = __float2bfloat16(acc[o] - __bfloat162float(h));
    }
    size_t off = (size_t)bc * HW_ + row * W_ + col0;
    *(uint4*)(g_s_hi + off)     = *(uint4*)&hi[0];
    *(uint4*)(g_s_hi + off + 8) = *(uint4*)&hi[8];
    *(uint4*)(g_s_lo + off)     = *(uint4*)&lo[0];
    *(uint4*)(g_s_lo + off + 8) = *(uint4*)&lo[8];
}

// ============================================================
// 5) pointwise GEMM via WMMA bf16 error-split (3 accumulating passes):
//    Y = PWhi*Shi + PWhi*Slo + PWlo*Shi   (fp32 accumulators)
//    CTA tile M=128 (o) x N=64 (hw), K=256 in 8 chunks of 32.
//    8 warps in 4x2 grid, warp tile 32x32 (2x2 wmma 16x16x16 frags).
//    A = PW [m][k] row-major; B = S [k][n] row-major (no transpose!).
// ============================================================
#define LDA 40   // bf16 elems per A smem row (32 + 8 pad); 80 B, /8 ok
#define LDB 72   // bf16 elems per B smem row (64 + 8 pad); 144 B, /8 ok

__global__ void __launch_bounds__(256)
pw_gemm_wmma(float* __restrict__ out) {
    __shared__ __nv_bfloat16 Ahi[128 * LDA], Alo[128 * LDA];
    __shared__ __nv_bfloat16 Bhi[32 * LDB],  Blo[32 * LDB];

    int tid = threadIdx.x, w = tid >> 5;
    int n0 = blockIdx.x * 64;
    int m0 = blockIdx.y * 128;
    int b  = blockIdx.z;
    int wm = (w & 3) * 32;      // warp m offset
    int wn = (w >> 2) * 32;     // warp n offset

    const __nv_bfloat16* Shi = g_s_hi + (size_t)b * C_ * HW_;
    const __nv_bfloat16* Slo = g_s_lo + (size_t)b * C_ * HW_;

    wmma::fragment<wmma::accumulator, 16, 16, 16, float> acc[2][2];
#pragma unroll
    for (int i = 0; i < 2; i++)
#pragma unroll
        for (int j = 0; j < 2; j++) wmma::fill_fragment(acc[i][j], 0.f);

    for (int kc = 0; kc < 8; kc++) {
        int kc0 = kc * 32;
        // ---- A tiles: 128 x 32 bf16, hi & lo (uint2 = 4 bf16) ----
#pragma unroll
        for (int q = 0; q < 4; q++) {
            int idx = q * 256 + tid;          // 1024 uint2 per buffer
            int row = idx >> 3, c8 = (idx & 7) * 4;
            *(uint2*)&Ahi[row * LDA + c8] =
                *(const uint2*)&g_pw_hi[(size_t)(m0 + row) * C_ + kc0 + c8];
            *(uint2*)&Alo[row * LDA + c8] =
                *(const uint2*)&g_pw_lo[(size_t)(m0 + row) * C_ + kc0 + c8];
        }
        // ---- B tiles: 32 x 64 bf16, hi & lo ----
#pragma unroll
        for (int q = 0; q < 2; q++) {
            int idx = q * 256 + tid;          // 512 uint2 per buffer
            int r = idx >> 4, c4 = (idx & 15) * 4;
            *(uint2*)&Bhi[r * LDB + c4] =
                *(const uint2*)&Shi[(size_t)(kc0 + r) * HW_ + n0 + c4];
            *(uint2*)&Blo[r * LDB + c4] =
                *(const uint2*)&Slo[(size_t)(kc0 + r) * HW_ + n0 + c4];
        }
        __syncthreads();

#pragma unroll
        for (int kk = 0; kk < 2; kk++) {
            wmma::fragment<wmma::matrix_a, 16, 16, 16, __nv_bfloat16, wmma::row_major> ah[2], al[2];
            wmma::fragment<wmma::matrix_b, 16, 16, 16, __nv_bfloat16, wmma::row_major> bh[2], bl[2];
#pragma unroll
            for (int i = 0; i < 2; i++) {
                wmma::load_matrix_sync(ah[i], &Ahi[(wm + i * 16) * LDA + kk * 16], LDA);
                wmma::load_matrix_sync(al[i], &Alo[(wm + i * 16) * LDA + kk * 16], LDA);
            }
#pragma unroll
            for (int j = 0; j < 2; j++) {
                wmma::load_matrix_sync(bh[j], &Bhi[kk * 16 * LDB + wn + j * 16], LDB);
                wmma::load_matrix_sync(bl[j], &Blo[kk * 16 * LDB + wn + j * 16], LDB);
            }
#pragma unroll
            for (int i = 0; i < 2; i++)
#pragma unroll
                for (int j = 0; j < 2; j++) {
                    wmma::mma_sync(acc[i][j], ah[i], bh[j], acc[i][j]);
                    wmma::mma_sync(acc[i][j], ah[i], bl[j], acc[i][j]);
                    wmma::mma_sync(acc[i][j], al[i], bh[j], acc[i][j]);
                }
        }
        __syncthreads();
    }

    // ---- epilogue: store fp32 accumulators to global ----
#pragma unroll
    for (int i = 0; i < 2; i++)
#pragma unroll
        for (int j = 0; j < 2; j++) {
            float* cp = out + (size_t)b * C_ * HW_
                      + (size_t)(m0 + wm + i * 16) * HW_ + n0 + wn + j * 16;
            wmma::store_matrix_sync(cp, acc[i][j], HW_, wmma::mem_row_major);
        }
}

// ============================================================
extern "C" void kernel_launch(void* const* d_in, const int* in_sizes, int n_in,
                              void* d_out, int out_size) {
    const float* x  = (const float*)d_in[0];
    const float* dw = (const float*)d_in[1];
    const float* pw = (const float*)d_in[2];
    const float* w1 = (const float*)d_in[3];
    const float* b1 = (const float*)d_in[4];
    const float* w2 = (const float*)d_in[5];
    const float* b2 = (const float*)d_in[6];
    float* out = (float*)d_out;

    pool_kernel   <<<B_ * C_, 256>>>(x);
    mlp_kernel    <<<B_, 64>>>(w1, b1);
    genw_kernel   <<<dim3(CKK_ / 128, B_), 128>>>(dw, w2, b2);
    pwsplit_kernel<<<C_ * C_ / 256, 256>>>(pw);
    dwconv_kernel <<<B_ * C_, 256>>>(x);
    pw_gemm_wmma  <<<dim3(HW_ / 64, C_ / 128, B_), 256>>>(out);
}

// round 16
// speedup vs baseline: 1.3468x; 1.0737x over previous
#include <cuda_runtime.h>
#include <cuda_bf16.h>
#include <mma.h>
#include <cstdint>
#include <math.h>

using namespace nvcuda;

#define B_    16
#define C_    256
#define H_    64
#define W_    64
#define K_    7
#define HW_   (H_*W_)      // 4096
#define KK_   (K_*K_)      // 49
#define CKK_  (C_*KK_)     // 12544
#define CMID_ 64

// ---- scratch (static device globals; no allocation) ----
__device__ float g_pooled[B_*C_];
__device__ float g_h[B_*CMID_];
__device__ float g_fused[B_*CKK_];
__device__ __nv_bfloat16 g_s_hi[(size_t)B_*C_*HW_];   // dwconv out, bf16 hi
__device__ __nv_bfloat16 g_s_lo[(size_t)B_*C_*HW_];   // dwconv out, bf16 lo
__device__ __nv_bfloat16 g_pw_hi[C_*C_];
__device__ __nv_bfloat16 g_pw_lo[C_*C_];

__device__ __forceinline__ uint32_t smem_u32(const void* p) {
    uint32_t a;
    asm("{ .reg .u64 t; cvta.to.shared.u64 t, %1; cvt.u32.u64 %0, t; }" : "=r"(a) : "l"(p));
    return a;
}
__device__ __forceinline__ void cp16(uint32_t s, const void* g) {
    asm volatile("cp.async.cg.shared.global [%0], [%1], 16;" :: "r"(s), "l"(g));
}

// ============================================================
// 1) global average pool
// ============================================================
__global__ void pool_kernel(const float* __restrict__ x) {
    int bc = blockIdx.x;
    const float4* xp = (const float4*)(x + (size_t)bc * HW_);
    int t = threadIdx.x;
    float s = 0.f;
#pragma unroll
    for (int it = 0; it < 4; it++) {
        float4 v = xp[t + it * 256];
        s += v.x + v.y + v.z + v.w;
    }
#pragma unroll
    for (int o = 16; o > 0; o >>= 1) s += __shfl_down_sync(0xffffffffu, s, o);
    __shared__ float ws[8];
    if ((t & 31) == 0) ws[t >> 5] = s;
    __syncthreads();
    if (t < 8) {
        float v = ws[t];
#pragma unroll
        for (int o = 4; o > 0; o >>= 1) v += __shfl_down_sync(0xffu, v, o);
        if (t == 0) g_pooled[bc] = v * (1.f / (float)HW_);
    }
}

// ============================================================
// 2) h = gelu(pooled @ w1.T + b1), exact GELU
// ============================================================
__global__ void mlp_kernel(const float* __restrict__ w1, const float* __restrict__ b1) {
    int b = blockIdx.x;
    __shared__ float ps[C_];
    int t = threadIdx.x;
    for (int i = t; i < C_; i += 64) ps[i] = g_pooled[b * C_ + i];
    __syncthreads();
    float acc = b1[t];
    const float* wr = w1 + t * C_;
#pragma unroll 8
    for (int kk = 0; kk < C_; kk++) acc += ps[kk] * wr[kk];
    float g = 0.5f * acc * (1.f + erff(acc * 0.70710678118654752f));
    g_h[b * CMID_ + t] = g;
}

// ============================================================
// 3) fused dynamic weights
// ============================================================
__global__ void genw_kernel(const float* __restrict__ dw,
                            const float* __restrict__ w2,
                            const float* __restrict__ b2) {
    int b = blockIdx.y;
    int r = blockIdx.x * 128 + threadIdx.x;
    __shared__ float hs[CMID_];
    if (threadIdx.x < CMID_) hs[threadIdx.x] = g_h[b * CMID_ + threadIdx.x];
    __syncthreads();
    float acc = b2[r] + dw[r];
    const float* wr = w2 + (size_t)r * CMID_;
#pragma unroll
    for (int kk = 0; kk < CMID_; kk++) acc += hs[kk] * wr[kk];
    g_fused[b * CKK_ + r] = acc;
}

// ============================================================
// 3b) split pw weights into bf16 hi/lo
// ============================================================
__global__ void pwsplit_kernel(const float* __restrict__ pw) {
    int i = blockIdx.x * 256 + threadIdx.x;
    float x = pw[i];
    __nv_bfloat16 h = __float2bfloat16(x);
    g_pw_hi[i] = h;
    g_pw_lo[i] = __float2bfloat16(x - __bfloat162float(h));
}

// ============================================================
// 4) per-instance depthwise 7x7, output bf16 hi/lo
// ============================================================
__global__ void __launch_bounds__(256) dwconv_kernel(const float* __restrict__ x) {
    __shared__ float sp[70 * 72];
    __shared__ float ws[KK_];
    int bc = blockIdx.x;
    int b = bc >> 8, c = bc & 255;
    const float* xp = x + (size_t)bc * HW_;
    int t = threadIdx.x;
    if (t < KK_) ws[t] = g_fused[b * CKK_ + c * KK_ + t];
    for (int s = t; s < 70 * 70; s += 256) {
        int r = s / 70, cc = s - r * 70;
        int gy = r - 3, gx = cc - 3;
        float v = 0.f;
        if (gy >= 0 && gy < H_ && gx >= 0 && gx < W_) v = xp[gy * W_ + gx];
        sp[r * 72 + cc] = v;
    }
    __syncthreads();

    int row = t >> 2, col0 = (t & 3) * 16;
    float acc[16];
#pragma unroll
    for (int o = 0; o < 16; o++) acc[o] = 0.f;
#pragma unroll
    for (int i = 0; i < K_; i++) {
        float wr[K_];
#pragma unroll
        for (int j = 0; j < K_; j++) wr[j] = ws[i * K_ + j];
        float4 xv4[6];
        const float* rp = &sp[(row + i) * 72 + col0];
#pragma unroll
        for (int q = 0; q < 6; q++) xv4[q] = *(const float4*)(rp + q * 4);
        const float* xv = (const float*)xv4;
#pragma unroll
        for (int j = 0; j < K_; j++)
#pragma unroll
            for (int o = 0; o < 16; o++)
                acc[o] += xv[o + j] * wr[j];
    }
    __align__(16) __nv_bfloat16 hi[16], lo[16];
#pragma unroll
    for (int o = 0; o < 16; o++) {
        __nv_bfloat16 h = __float2bfloat16(acc[o]);
        hi[o] = h;
        lo[o] = __float2bfloat16(acc[o] - __bfloat162float(h));
    }
    size_t off = (size_t)bc * HW_ + row * W_ + col0;
    *(uint4*)(g_s_hi + off)     = *(uint4*)&hi[0];
    *(uint4*)(g_s_hi + off + 8) = *(uint4*)&hi[8];
    *(uint4*)(g_s_lo + off)     = *(uint4*)&lo[0];
    *(uint4*)(g_s_lo + off + 8) = *(uint4*)&lo[8];
}

// ============================================================
// 5) pointwise GEMM, WMMA bf16 error-split, double-buffered cp.async.
//    CTA tile M=128 x N=128, K=256 in 8 chunks of 32, 2 smem stages.
//    8 warps (4 M x 2 N), warp tile 32x64, acc[2][4].
// ============================================================
#define LDA 40    // A row pitch, bf16 elems (32+8); 80 B
#define LDB 136   // B row pitch, bf16 elems (128+8); 272 B
#define PG_AHI   0
#define PG_ALO   10240                   // 128*80
#define PG_BHI   20480
#define PG_BLO   29184                   // +32*272 = 8704
#define PG_STAGE 37888
#define PG_TOTAL (2*PG_STAGE)            // 75776 B

__global__ void __launch_bounds__(256)
pw_gemm_wmma(float* __restrict__ out) {
    extern __shared__ __align__(128) char dsmem[];
    uint32_t sb = smem_u32(dsmem);

    int tid = threadIdx.x, w = tid >> 5;
    int n0 = blockIdx.x * 128;
    int m0 = blockIdx.y * 128;
    int b  = blockIdx.z;
    int wm = (w & 3) * 32;      // warp m offset
    int wn = (w >> 2) * 64;     // warp n offset

    const __nv_bfloat16* Shi = g_s_hi + (size_t)b * C_ * HW_;
    const __nv_bfloat16* Slo = g_s_lo + (size_t)b * C_ * HW_;

    auto load_chunk = [&](int kc, int st) {
        int kc0 = kc * 32;
        uint32_t base = sb + st * PG_STAGE;
        // A: 128 x 32 bf16, hi+lo. 512 x 16B chunks per buffer; 2 iters.
#pragma unroll
        for (int q = 0; q < 2; q++) {
            int idx = q * 256 + tid;
            int row = idx >> 2, c = (idx & 3) * 8;
            cp16(base + PG_AHI + row * 80 + c * 2,
                 &g_pw_hi[(size_t)(m0 + row) * C_ + kc0 + c]);
            cp16(base + PG_ALO + row * 80 + c * 2,
                 &g_pw_lo[(size_t)(m0 + row) * C_ + kc0 + c]);
        }
        // B: 32 x 128 bf16, hi+lo. 512 x 16B chunks per buffer; 2 iters.
#pragma unroll
        for (int q = 0; q < 2; q++) {
            int idx = q * 256 + tid;
            int row = idx >> 4, c = (idx & 15) * 8;
            cp16(base + PG_BHI + row * 272 + c * 2,
                 &Shi[(size_t)(kc0 + row) * HW_ + n0 + c]);
            cp16(base + PG_BLO + row * 272 + c * 2,
                 &Slo[(size_t)(kc0 + row) * HW_ + n0 + c]);
        }
        asm volatile("cp.async.commit_group;");
    };

    wmma::fragment<wmma::accumulator, 16, 16, 16, float> acc[2][4];
#pragma unroll
    for (int i = 0; i < 2; i++)
#pragma unroll
        for (int j = 0; j < 4; j++) wmma::fill_fragment(acc[i][j], 0.f);

    load_chunk(0, 0);

    for (int kc = 0; kc < 8; kc++) {
        int st = kc & 1;
        if (kc < 7) {
            load_chunk(kc + 1, st ^ 1);
            asm volatile("cp.async.wait_group 1;");
        } else {
            asm volatile("cp.async.wait_group 0;");
        }
        __syncthreads();

        const __nv_bfloat16* Ah = (const __nv_bfloat16*)(dsmem + st * PG_STAGE + PG_AHI);
        const __nv_bfloat16* Al = (const __nv_bfloat16*)(dsmem + st * PG_STAGE + PG_ALO);
        const __nv_bfloat16* Bh = (const __nv_bfloat16*)(dsmem + st * PG_STAGE + PG_BHI);
        const __nv_bfloat16* Bl = (const __nv_bfloat16*)(dsmem + st * PG_STAGE + PG_BLO);

#pragma unroll
        for (int kk = 0; kk < 2; kk++) {
            wmma::fragment<wmma::matrix_a, 16, 16, 16, __nv_bfloat16, wmma::row_major> ah[2], al[2];
            wmma::fragment<wmma::matrix_b, 16, 16, 16, __nv_bfloat16, wmma::row_major> bh[4], bl[4];
#pragma unroll
            for (int i = 0; i < 2; i++) {
                wmma::load_matrix_sync(ah[i], &Ah[(wm + i * 16) * LDA + kk * 16], LDA);
                wmma::load_matrix_sync(al[i], &Al[(wm + i * 16) * LDA + kk * 16], LDA);
            }
#pragma unroll
            for (int j = 0; j < 4; j++) {
                wmma::load_matrix_sync(bh[j], &Bh[kk * 16 * LDB + wn + j * 16], LDB);
                wmma::load_matrix_sync(bl[j], &Bl[kk * 16 * LDB + wn + j * 16], LDB);
            }
#pragma unroll
            for (int i = 0; i < 2; i++)
#pragma unroll
                for (int j = 0; j < 4; j++) {
                    wmma::mma_sync(acc[i][j], ah[i], bh[j], acc[i][j]);
                    wmma::mma_sync(acc[i][j], ah[i], bl[j], acc[i][j]);
                    wmma::mma_sync(acc[i][j], al[i], bh[j], acc[i][j]);
                }
        }
        __syncthreads();
    }

    // ---- epilogue ----
#pragma unroll
    for (int i = 0; i < 2; i++)
#pragma unroll
        for (int j = 0; j < 4; j++) {
            float* cp = out + (size_t)b * C_ * HW_
                      + (size_t)(m0 + wm + i * 16) * HW_ + n0 + wn + j * 16;
            wmma::store_matrix_sync(cp, acc[i][j], HW_, wmma::mem_row_major);
        }
}

// ============================================================
extern "C" void kernel_launch(void* const* d_in, const int* in_sizes, int n_in,
                              void* d_out, int out_size) {
    const float* x  = (const float*)d_in[0];
    const float* dw = (const float*)d_in[1];
    const float* pw = (const float*)d_in[2];
    const float* w1 = (const float*)d_in[3];
    const float* b1 = (const float*)d_in[4];
    const float* w2 = (const float*)d_in[5];
    const float* b2 = (const float*)d_in[6];
    float* out = (float*)d_out;

    cudaFuncSetAttribute(pw_gemm_wmma, cudaFuncAttributeMaxDynamicSharedMemorySize, PG_TOTAL);

    pool_kernel   <<<B_ * C_, 256>>>(x);
    mlp_kernel    <<<B_, 64>>>(w1, b1);
    genw_kernel   <<<dim3(CKK_ / 128, B_), 128>>>(dw, w2, b2);
    pwsplit_kernel<<<C_ * C_ / 256, 256>>>(pw);
    dwconv_kernel <<<B_ * C_, 256>>>(x);
    pw_gemm_wmma  <<<dim3(HW_ / 128, C_ / 128, B_), 256, PG_TOTAL>>>(out);
}